// round 15
// baseline (speedup 1.0000x reference)
#include <cuda_runtime.h>
#include <cuda_bf16.h>
#include <cuda_fp16.h>
#include <cstdint>
#include <math.h>

#define BB 4
#define SS 2048
#define DD 512
#define TILE_B 10240              // one 128x32 fp16 tile, LDT=40 padded rows

// ---------------------------------------------------------------------------
// Scratch globals. fp16 operands stored TILED: [rowtile][ktile] blocks of
// TILE_B bytes (128 rows x 80B), exactly the smem format consumed by ldmatrix.
// ---------------------------------------------------------------------------
__device__ __align__(16) unsigned char g_xh_t[64*16*TILE_B], g_xl_t[64*16*TILE_B];
__device__ __align__(16) unsigned char g_Wh_t[3][4*16*TILE_B];
__device__ __align__(16) unsigned char g_qmh_t[64*16*TILE_B], g_qml_t[64*16*TILE_B];
__device__ __align__(16) unsigned char g_kmh_t[64*16*TILE_B];
__device__ __align__(16) unsigned char g_vTh_t[16*64*TILE_B];
__device__ __align__(16) unsigned char g_ah_t[(size_t)64*64*TILE_B], g_al_t[(size_t)64*64*TILE_B];
__device__ float g_q[BB*SS*DD], g_k[BB*SS*DD];
__device__ float g_qn2[BB*SS], g_kn2[BB*SS];
__device__ float g_scores[(size_t)BB*SS*SS];
__device__ float g_attn_fb[(size_t)BB*SS*SS];

// byte offset of element (row, col) in a tiled fp16 matrix with nkt k-tiles
__device__ __forceinline__ size_t toff(int row, int col, int nkt) {
    return ((size_t)((row >> 7) * nkt + (col >> 5))) * TILE_B
         + (size_t)((row & 127) * 80 + (((col >> 3) & 3) << 4) + ((col & 7) << 1));
}
__device__ __forceinline__ void put_h(unsigned char* base, int row, int col, int nkt, __half v) {
    *(__half*)(base + toff(row, col, nkt)) = v;
}
__device__ __forceinline__ void put_h2(unsigned char* base, int row, int col, int nkt, __half2 v) {
    *(__half2*)(base + toff(row, col, nkt)) = v;   // col must be even, col%8 <= 6
}

// ---------------------------------------------------------------------------
__device__ __forceinline__ uint32_t smem_u32(const void* p) {
    uint32_t a;
    asm("{ .reg .u64 t; cvta.to.shared.u64 t, %1; cvt.u32.u64 %0, t; }" : "=r"(a) : "l"(p));
    return a;
}

__device__ __forceinline__ void ldsm_x4(uint32_t* r, uint32_t addr) {
    asm volatile("ldmatrix.sync.aligned.m8n8.x4.shared.b16 {%0,%1,%2,%3}, [%4];"
        : "=r"(r[0]), "=r"(r[1]), "=r"(r[2]), "=r"(r[3]) : "r"(addr));
}

__device__ __forceinline__ void mma_f16(float* d, const uint32_t* a, const uint32_t* b) {
    asm volatile("mma.sync.aligned.m16n8k16.row.col.f32.f16.f16.f32 "
        "{%0,%1,%2,%3}, {%4,%5,%6,%7}, {%8,%9}, {%0,%1,%2,%3};"
        : "+f"(d[0]), "+f"(d[1]), "+f"(d[2]), "+f"(d[3])
        : "r"(a[0]), "r"(a[1]), "r"(a[2]), "r"(a[3]), "r"(b[0]), "r"(b[1]));
}

__device__ __forceinline__ void tma1d(uint32_t dst, const void* src, uint32_t bytes, uint32_t bar) {
    asm volatile("cp.async.bulk.shared::cluster.global.mbarrier::complete_tx::bytes "
        "[%0], [%1], %2, [%3];"
        :: "r"(dst), "l"(src), "r"(bytes), "r"(bar) : "memory");
}

#define MBARRIER_INIT(addr, count) \
    asm volatile("mbarrier.init.shared.b64 [%0], %1;" \
        :: "r"((uint32_t)(addr)), "r"((uint32_t)(count)) : "memory")

#define MBARRIER_EXPECT_TX(addr, bytes) \
    asm volatile("mbarrier.arrive.expect_tx.shared.b64 _, [%0], %1;" \
        :: "r"((uint32_t)(addr)), "r"((uint32_t)(bytes)) : "memory")

#define MBARRIER_WAIT_PARITY(addr, parity) do { \
    uint32_t _m = (uint32_t)(addr); \
    uint32_t _p = (uint32_t)(parity); \
    uint32_t _done; \
    asm volatile( \
        "{\n\t.reg .pred p;\n\t" \
        "mbarrier.try_wait.parity.acquire.cta.shared::cta.b64 p, [%1], %2;\n\t" \
        "selp.b32 %0, 1, 0, p;\n\t}" \
        : "=r"(_done) : "r"(_m), "r"(_p) : "memory"); \
    if (!_done) { \
        asm volatile( \
            "{\n\t.reg .pred P1;\n\t" \
            "WL_%=:\n\t" \
            "mbarrier.try_wait.parity.acquire.cta.shared::cta.b64 P1, [%0], %1, 0x989680;\n\t" \
            "@P1 bra.uni WD_%=;\n\t" \
            "bra.uni WL_%=;\n\t" \
            "WD_%=:\n\t}" \
            :: "r"(_m), "r"(_p) : "memory"); \
    } \
} while(0)

#define FENCE_PROXY_ASYNC() asm volatile("fence.proxy.async.shared::cta;" ::: "memory")

__device__ __forceinline__ void curv_params(const float* __restrict__ craw,
                                            float& kval, float& absk, float& sk, int& branch) {
    float k = -2.0f + 2.0f * (tanhf(craw[0]) + 1.0f);
    kval = k;
    absk = fabsf(k);
    sk = sqrtf(fmaxf(absk, 1e-5f));
    branch = (absk < 0.01f) ? 0 : ((k < 0.0f) ? 1 : 2);
}

// ---------------------------------------------------------------------------
// Tensor-core GEMM: fp16 EC, D = (Ah [+ Al]) * Bh  (USELO toggles the Al term).
// 256 threads (8 warps), CTA tile 128x128, warp tile 32x64, K-chunk 32,
// TMA-1D 3-stage pipeline, 2 CTAs/SM.
// MODE: 0 = QKV (z picks Q/K/V), 1 = scores, 2 = attn @ V
// ---------------------------------------------------------------------------
#define LDT 40
#define BUFSZ (3 * TILE_B)                // Ah Al Bh = 30720
#define NSTAGE 3
#define BAR_OFF (NSTAGE * BUFSZ)          // 92160
#define SMEM_DYN (NSTAGE * BUFSZ + 64)

template<int MODE, int USELO>
__global__ __launch_bounds__(256, 2)
void gemm_tc(const float* __restrict__ bq, const float* __restrict__ bk,
             const float* __restrict__ bv,
             const float* __restrict__ craw, const float* __restrict__ temp,
             float* __restrict__ outp, int zoff) {
    const int m0 = blockIdx.y * 128;
    const int n0 = blockIdx.x * 128;
    if (MODE == 1 && blockIdx.x > blockIdx.y) return;   // causal tile skip

    extern __shared__ __align__(128) char smem[];

    const int tid  = threadIdx.x;
    const int wid  = tid >> 5;
    const int lane = tid & 31;
    const int wm   = wid >> 1;       // 0..3 -> rows wm*32..+31
    const int wn   = wid & 1;        // 0..1 -> cols wn*64..+63
    const int z    = blockIdx.z + zoff;

    const unsigned char *tAh, *tAl, *tBh;
    int nktA, nktB, rbA, rbB, kC;
    if (MODE == 0) {
        tAh = g_xh_t; tAl = g_xl_t; nktA = 16; rbA = m0;
        tBh = g_Wh_t[z]; nktB = 16; rbB = n0;
        kC = 16;
    } else if (MODE == 1) {
        tAh = g_qmh_t; tAl = g_qml_t; nktA = 16; rbA = z * SS + m0;
        tBh = g_kmh_t; nktB = 16; rbB = z * SS + n0;
        kC = 16;
    } else {
        tAh = g_ah_t; tAl = g_al_t; nktA = 64; rbA = z * SS + m0;
        tBh = g_vTh_t; nktB = 64; rbB = z * DD + n0;
        kC = 4 * (blockIdx.y + 1);   // causal K truncation (>= 4)
    }

    const uint32_t usm = smem_u32(smem);
    const size_t baseA = (size_t)(rbA >> 7) * nktA;
    const size_t baseB = (size_t)(rbB >> 7) * nktB;

    auto preload = [&](int st, int ch) {
        uint32_t bar = usm + BAR_OFF + st * 8;
        MBARRIER_EXPECT_TX(bar, (USELO ? 3 : 2) * TILE_B);
        uint32_t ub = usm + st * BUFSZ;
        tma1d(ub,              tAh + (baseA + ch) * TILE_B, TILE_B, bar);
        if (USELO)
            tma1d(ub + TILE_B, tAl + (baseA + ch) * TILE_B, TILE_B, bar);
        tma1d(ub + 2 * TILE_B, tBh + (baseB + ch) * TILE_B, TILE_B, bar);
    };

    if (tid == 0) {
        MBARRIER_INIT(usm + BAR_OFF, 1);
        MBARRIER_INIT(usm + BAR_OFF + 8, 1);
        MBARRIER_INIT(usm + BAR_OFF + 16, 1);
    }
    __syncthreads();
    FENCE_PROXY_ASYNC();
    if (tid == 0) { preload(0, 0); preload(1, 1); preload(2, 2); }   // kC >= 4 always

    float acc[2][8][4] = {};   // warp tile 32x64: 2 m16-tiles x 8 n8-tiles

    const int a_row = lane & 15;
    const int a_ko  = (lane >> 4) << 3;
    const int b_row = (lane & 7) + ((lane >> 4) << 3);
    const int b_ko  = ((lane >> 3) & 1) << 3;

    for (int ch = 0; ch < kC; ++ch) {
        const int st = ch % NSTAGE;
        const int parity = (ch / NSTAGE) & 1;
        MBARRIER_WAIT_PARITY(usm + BAR_OFF + st * 8, parity);

        const uint32_t uAh = usm + st * BUFSZ;
        const uint32_t uAl = uAh + TILE_B;
        const uint32_t uBh = uAh + 2 * TILE_B;

        #pragma unroll
        for (int ks = 0; ks < 2; ++ks) {
            const int kb = ks * 16;
            uint32_t ah[2][4], al[2][4];
            #pragma unroll
            for (int i = 0; i < 2; ++i) {
                uint32_t off = (uint32_t)((wm * 32 + i * 16 + a_row) * LDT + kb + a_ko) * 2;
                ldsm_x4(ah[i], uAh + off);
                if (USELO) ldsm_x4(al[i], uAl + off);
            }
            #pragma unroll
            for (int p = 0; p < 4; ++p) {
                uint32_t off = (uint32_t)((wn * 64 + p * 16 + b_row) * LDT + kb + b_ko) * 2;
                uint32_t rh[4];
                ldsm_x4(rh, uBh + off);
                uint32_t b0h[2] = {rh[0], rh[1]}, b1h[2] = {rh[2], rh[3]};
                #pragma unroll
                for (int i = 0; i < 2; ++i) {
                    mma_f16(acc[i][2*p],   ah[i], b0h);
                    if (USELO) mma_f16(acc[i][2*p], al[i], b0h);
                    mma_f16(acc[i][2*p+1], ah[i], b1h);
                    if (USELO) mma_f16(acc[i][2*p+1], al[i], b1h);
                }
            }
        }
        __syncthreads();                     // all ldsm of stage st consumed
        if (tid == 0 && ch + NSTAGE < kC) preload(st, ch + NSTAGE);
    }

    // ---- epilogue: 4 passes of 32 rows staged through smem ----
    float (*stg)[132] = (float (*)[132])smem;   // 16896 B, below BAR_OFF

    float kv, absk, sk; int branch;
    float invT = 1.0f;
    if (MODE == 1) {
        curv_params(craw, kv, absk, sk, branch);
        invT = 1.0f / (temp[0] + 1e-8f);
    }
    const float* bias = (MODE == 0) ? ((z == 0) ? bq : (z == 1) ? bk : bv) : nullptr;

    #pragma unroll 1
    for (int h = 0; h < 4; ++h) {
        __syncthreads();
        if (wm == h) {
            #pragma unroll
            for (int i = 0; i < 2; ++i)
                #pragma unroll
                for (int j = 0; j < 8; ++j) {
                    int r = i * 16 + (lane >> 2);
                    int c = wn * 64 + j * 8 + 2 * (lane & 3);
                    stg[r][c]     = acc[i][j][0];
                    stg[r][c+1]   = acc[i][j][1];
                    stg[r+8][c]   = acc[i][j][2];
                    stg[r+8][c+1] = acc[i][j][3];
                }
        }
        __syncthreads();

        if (MODE == 0 && z == 2) {
            // V: write transposed fp16 (hi only) into tiled vT
            #pragma unroll 2
            for (int it = 0; it < 16; ++it) {
                int idx = it * 256 + tid;
                int rr = idx & 31, cc = idx >> 5;       // cc 0..127
                float v = stg[rr][cc] + bias[n0 + cc];
                int m = m0 + h * 32 + rr, b = m >> 11, j = m & (SS - 1);
                put_h(g_vTh_t, b * DD + n0 + cc, j, 64, __float2half(v));
            }
        } else if (MODE == 0) {
            float* dst = (z == 0) ? g_q : g_k;
            #pragma unroll 2
            for (int it = 0; it < 16; ++it) {
                int idx = it * 256 + tid;
                int rr = idx >> 7, cc = idx & 127;
                float v = stg[rr][cc] + bias[n0 + cc];
                dst[(size_t)(m0 + h * 32 + rr) * DD + n0 + cc] = v;
            }
        } else if (MODE == 1) {
            const float* qn2 = g_qn2 + z * SS;
            const float* kn2 = g_kn2 + z * SS;
            float* dst = g_scores + (size_t)z * SS * SS;
            #pragma unroll 2
            for (int it = 0; it < 16; ++it) {
                int idx = it * 256 + tid;
                int rr = idx >> 7, cc = idx & 127;
                float dot = stg[rr][cc];
                float qq = qn2[m0 + h * 32 + rr];
                float kk = kn2[n0 + cc];
                float dist;
                if (branch == 0) {
                    float d2 = fmaxf(qq + kk - 2.0f * dot, 0.0f);
                    dist = sqrtf(d2 + 1e-12f);
                } else if (branch == 1) {
                    float d2 = fmaxf(qq + kk - 2.0f * dot, 0.0f);
                    float den = fmaxf((1.0f - absk * qq) * (1.0f - absk * kk), 1e-5f);
                    float arg = 1.0f + 2.0f * absk * d2 / den;
                    dist = acoshf(fmaxf(arg, 1.0f + 1e-7f)) / sk;
                } else {
                    float c = fminf(fmaxf(absk * dot, -1.0f + 1e-7f), 1.0f - 1e-7f);
                    dist = acosf(c) / sk;
                }
                dst[(size_t)(m0 + h * 32 + rr) * SS + n0 + cc] = -dist * invT;
            }
        } else {
            float* dst = outp + (size_t)z * SS * DD;
            #pragma unroll 2
            for (int it = 0; it < 16; ++it) {
                int idx = it * 256 + tid;
                int rr = idx >> 7, cc = idx & 127;
                dst[(size_t)(m0 + h * 32 + rr) * DD + n0 + cc] = stg[rr][cc];
            }
        }
    }
}

// ---------------------------------------------------------------------------
// Fused fp32 -> fp16 split: x (hi+lo), Wq/Wk/Wv (hi only)
// ---------------------------------------------------------------------------
#define NX (BB*SS*DD)
#define NW (DD*DD)

__global__ __launch_bounds__(256)
void split_all(const float* __restrict__ x, const float* __restrict__ wq,
               const float* __restrict__ wk, const float* __restrict__ wv) {
    int i = blockIdx.x * 256 + threadIdx.x;
    if (i < NX) {
        float v = x[i];
        int row = i / DD, col = i % DD;
        __half hi = __float2half(v);
        put_h(g_xh_t, row, col, 16, hi);
        put_h(g_xl_t, row, col, 16, __float2half(v - __half2float(hi)));
    } else {
        const float* src; unsigned char* th; int off;
        if (i < NX + NW)        { src = wq; th = g_Wh_t[0]; off = i - NX; }
        else if (i < NX + 2*NW) { src = wk; th = g_Wh_t[1]; off = i - NX - NW; }
        else                    { src = wv; th = g_Wh_t[2]; off = i - NX - 2*NW; }
        float v = src[off];
        put_h(th, off / DD, off % DD, 16, __float2half(v));
    }
}

// ---------------------------------------------------------------------------
// Projection: q -> tiled fp16 hi+lo; k -> tiled fp16 hi only; plus |.|^2
// ---------------------------------------------------------------------------
__global__ __launch_bounds__(128)
void project_kernel(const float* __restrict__ craw) {
    float kval, absk, sk; int branch;
    curv_params(craw, kval, absk, sk, branch);

    const int row = blockIdx.x;                  // global 0..8191
    const int isq = (blockIdx.y == 0);
    const float* src = (isq ? g_q : g_k) + (size_t)row * DD;
    float* n2out = isq ? g_qn2 : g_kn2;
    const int t = threadIdx.x;

    float v4[4]; float s = 0.f;
    #pragma unroll
    for (int u = 0; u < 4; u++) { v4[u] = src[t + u * 128]; s += v4[u] * v4[u]; }

    __shared__ float red[4];
    #pragma unroll
    for (int o = 16; o > 0; o >>= 1) s += __shfl_xor_sync(0xffffffffu, s, o);
    if ((t & 31) == 0) red[t >> 5] = s;
    __syncthreads();
    float sum = red[0] + red[1] + red[2] + red[3];

    float scale;
    if (branch == 0) {
        scale = 1.0f;
    } else if (branch == 1) {
        float n = sqrtf(sum + 1e-12f);
        float mx = (1.0f - 1e-3f) / sk;
        scale = fminf(1.0f, mx / n);
    } else {
        float n = sqrtf(sum + 1e-12f);
        scale = 1.0f / (n * sk);
    }
    #pragma unroll
    for (int u = 0; u < 4; u++) {
        float pv = v4[u] * scale;
        __half h = __float2half(pv);
        if (isq) {
            put_h(g_qmh_t, row, t + u * 128, 16, h);
            put_h(g_qml_t, row, t + u * 128, 16, __float2half(pv - __half2float(h)));
        } else {
            put_h(g_kmh_t, row, t + u * 128, 16, h);
        }
    }
    if (t == 0) n2out[row] = sum * scale * scale;
}

// ---------------------------------------------------------------------------
// Causal row softmax -> fp32 attention (d_out) + tiled fp16 hi/lo (vectorized)
// ---------------------------------------------------------------------------
__global__ __launch_bounds__(256)
void softmax_kernel(float* __restrict__ attn) {
    const int row = blockIdx.x;         // b*S + i
    const int i = row & (SS - 1);
    const float4* s4 = (const float4*)(g_scores + (size_t)row * SS);
    float4* a4 = (float4*)(attn + (size_t)row * SS);
    const int t = threadIdx.x;

    float vals[8];
    float mx = -1e30f;
    #pragma unroll
    for (int u = 0; u < 2; ++u) {
        int idx = u * 256 + t;
        float4 vv = s4[idx];
        int j0 = idx * 4;
        vals[u*4+0] = (j0     <= i) ? vv.x : -1e30f;
        vals[u*4+1] = (j0 + 1 <= i) ? vv.y : -1e30f;
        vals[u*4+2] = (j0 + 2 <= i) ? vv.z : -1e30f;
        vals[u*4+3] = (j0 + 3 <= i) ? vv.w : -1e30f;
        mx = fmaxf(mx, fmaxf(fmaxf(vals[u*4], vals[u*4+1]), fmaxf(vals[u*4+2], vals[u*4+3])));
    }

    __shared__ float red[8];
    #pragma unroll
    for (int o = 16; o > 0; o >>= 1) mx = fmaxf(mx, __shfl_xor_sync(0xffffffffu, mx, o));
    if ((t & 31) == 0) red[t >> 5] = mx;
    __syncthreads();
    mx = red[0];
    #pragma unroll
    for (int w = 1; w < 8; w++) mx = fmaxf(mx, red[w]);
    __syncthreads();

    float sum = 0.f;
    #pragma unroll
    for (int u = 0; u < 8; ++u) {
        float e = expf(vals[u] - mx);   // masked entries: exp(-1e30) == 0
        vals[u] = e;
        sum += e;
    }
    #pragma unroll
    for (int o = 16; o > 0; o >>= 1) sum += __shfl_xor_sync(0xffffffffu, sum, o);
    if ((t & 31) == 0) red[t >> 5] = sum;
    __syncthreads();
    float tot = 0.f;
    #pragma unroll
    for (int w = 0; w < 8; w++) tot += red[w];
    float inv = 1.0f / tot;

    #pragma unroll
    for (int u = 0; u < 2; ++u) {
        int idx = u * 256 + t;
        int j0 = idx * 4;
        float4 pv;
        pv.x = vals[u*4+0] * inv;
        pv.y = vals[u*4+1] * inv;
        pv.z = vals[u*4+2] * inv;
        pv.w = vals[u*4+3] * inv;
        a4[idx] = pv;
        __half hx = __float2half(pv.x), hy = __float2half(pv.y);
        __half hz = __float2half(pv.z), hw = __float2half(pv.w);
        put_h2(g_ah_t, row, j0,     64, __halves2half2(hx, hy));
        put_h2(g_ah_t, row, j0 + 2, 64, __halves2half2(hz, hw));
        __half lx = __float2half(pv.x - __half2float(hx));
        __half ly = __float2half(pv.y - __half2float(hy));
        __half lz = __float2half(pv.z - __half2float(hz));
        __half lw = __float2half(pv.w - __half2float(hw));
        put_h2(g_al_t, row, j0,     64, __halves2half2(lx, ly));
        put_h2(g_al_t, row, j0 + 2, 64, __halves2half2(lz, lw));
    }
}

// ---------------------------------------------------------------------------
extern "C" void kernel_launch(void* const* d_in, const int* in_sizes, int n_in,
                              void* d_out, int out_size) {
    const float* x    = (const float*)d_in[0];
    const float* Wq   = (const float*)d_in[1];
    const float* bq   = (const float*)d_in[2];
    const float* Wk   = (const float*)d_in[3];
    const float* bk   = (const float*)d_in[4];
    const float* Wv   = (const float*)d_in[5];
    const float* bv   = (const float*)d_in[6];
    const float* craw = (const float*)d_in[7];
    const float* temp = (const float*)d_in[8];

    float* out = (float*)d_out;
    const size_t out_elems = (size_t)BB * SS * DD;
    const size_t attn_elems = (size_t)BB * SS * SS;

    float* attn_ptr;
    if ((size_t)out_size >= out_elems + attn_elems) {
        attn_ptr = out + out_elems;
    } else {
        void* p = nullptr;
        cudaGetSymbolAddress(&p, g_attn_fb);
        attn_ptr = (float*)p;
    }

    cudaFuncSetAttribute(gemm_tc<0,1>, cudaFuncAttributeMaxDynamicSharedMemorySize, SMEM_DYN);
    cudaFuncSetAttribute(gemm_tc<0,0>, cudaFuncAttributeMaxDynamicSharedMemorySize, SMEM_DYN);
    cudaFuncSetAttribute(gemm_tc<1,1>, cudaFuncAttributeMaxDynamicSharedMemorySize, SMEM_DYN);
    cudaFuncSetAttribute(gemm_tc<2,1>, cudaFuncAttributeMaxDynamicSharedMemorySize, SMEM_DYN);

    split_all<<<(NX + 3*NW)/256, 256>>>(x, Wq, Wk, Wv);
    // Q, K projections: 2-product EC
    gemm_tc<0,1><<<dim3(DD/128, (BB*SS)/128, 2), 256, SMEM_DYN>>>(bq, bk, bv, craw, temp, nullptr, 0);
    // V projection: 1-product (output is rounded to fp16 anyway)
    gemm_tc<0,0><<<dim3(DD/128, (BB*SS)/128, 1), 256, SMEM_DYN>>>(bq, bk, bv, craw, temp, nullptr, 2);
    project_kernel<<<dim3(BB*SS, 2), 128>>>(craw);
    gemm_tc<1,1><<<dim3(SS/128, SS/128, BB), 256, SMEM_DYN>>>(bq, bk, bv, craw, temp, nullptr, 0);
    softmax_kernel<<<BB*SS, 256>>>(attn_ptr);
    gemm_tc<2,1><<<dim3(DD/128, SS/128, BB), 256, SMEM_DYN>>>(bq, bk, bv, craw, temp, out, 0);
}

// round 16
// speedup vs baseline: 1.0261x; 1.0261x over previous
#include <cuda_runtime.h>
#include <cuda_bf16.h>
#include <cuda_fp16.h>
#include <cstdint>
#include <math.h>

#define BB 4
#define SS 2048
#define DD 512
#define TILE_B 10240              // one 128x32 fp16 tile, LDT=40 padded rows

// ---------------------------------------------------------------------------
// Scratch globals. fp16 operands stored TILED: [rowtile][ktile] blocks of
// TILE_B bytes (128 rows x 80B), exactly the smem format consumed by ldmatrix.
// ---------------------------------------------------------------------------
__device__ __align__(16) unsigned char g_xh_t[64*16*TILE_B], g_xl_t[64*16*TILE_B];
__device__ __align__(16) unsigned char g_Wh_t[3][4*16*TILE_B];
__device__ __align__(16) unsigned char g_qmh_t[64*16*TILE_B], g_qml_t[64*16*TILE_B];
__device__ __align__(16) unsigned char g_kmh_t[64*16*TILE_B];
__device__ __align__(16) unsigned char g_vTh_t[16*64*TILE_B];
__device__ __align__(16) unsigned char g_ah_t[(size_t)64*64*TILE_B], g_al_t[(size_t)64*64*TILE_B];
__device__ float g_q[BB*SS*DD], g_k[BB*SS*DD];
__device__ float g_qn2[BB*SS], g_kn2[BB*SS];
__device__ float g_scores[(size_t)BB*SS*SS];
__device__ float g_attn_fb[(size_t)BB*SS*SS];

// byte offset of element (row, col) in a tiled fp16 matrix with nkt k-tiles
__device__ __forceinline__ size_t toff(int row, int col, int nkt) {
    return ((size_t)((row >> 7) * nkt + (col >> 5))) * TILE_B
         + (size_t)((row & 127) * 80 + (((col >> 3) & 3) << 4) + ((col & 7) << 1));
}
__device__ __forceinline__ void put_h(unsigned char* base, int row, int col, int nkt, __half v) {
    *(__half*)(base + toff(row, col, nkt)) = v;
}
__device__ __forceinline__ void put_h2(unsigned char* base, int row, int col, int nkt, __half2 v) {
    *(__half2*)(base + toff(row, col, nkt)) = v;   // col must be even, col%8 <= 6
}

// ---------------------------------------------------------------------------
__device__ __forceinline__ uint32_t smem_u32(const void* p) {
    uint32_t a;
    asm("{ .reg .u64 t; cvta.to.shared.u64 t, %1; cvt.u32.u64 %0, t; }" : "=r"(a) : "l"(p));
    return a;
}

__device__ __forceinline__ void ldsm_x4(uint32_t* r, uint32_t addr) {
    asm volatile("ldmatrix.sync.aligned.m8n8.x4.shared.b16 {%0,%1,%2,%3}, [%4];"
        : "=r"(r[0]), "=r"(r[1]), "=r"(r[2]), "=r"(r[3]) : "r"(addr));
}

__device__ __forceinline__ void mma_f16(float* d, const uint32_t* a, const uint32_t* b) {
    asm volatile("mma.sync.aligned.m16n8k16.row.col.f32.f16.f16.f32 "
        "{%0,%1,%2,%3}, {%4,%5,%6,%7}, {%8,%9}, {%0,%1,%2,%3};"
        : "+f"(d[0]), "+f"(d[1]), "+f"(d[2]), "+f"(d[3])
        : "r"(a[0]), "r"(a[1]), "r"(a[2]), "r"(a[3]), "r"(b[0]), "r"(b[1]));
}

__device__ __forceinline__ void tma1d(uint32_t dst, const void* src, uint32_t bytes, uint32_t bar) {
    asm volatile("cp.async.bulk.shared::cluster.global.mbarrier::complete_tx::bytes "
        "[%0], [%1], %2, [%3];"
        :: "r"(dst), "l"(src), "r"(bytes), "r"(bar) : "memory");
}

#define MBARRIER_INIT(addr, count) \
    asm volatile("mbarrier.init.shared.b64 [%0], %1;" \
        :: "r"((uint32_t)(addr)), "r"((uint32_t)(count)) : "memory")

#define MBARRIER_EXPECT_TX(addr, bytes) \
    asm volatile("mbarrier.arrive.expect_tx.shared.b64 _, [%0], %1;" \
        :: "r"((uint32_t)(addr)), "r"((uint32_t)(bytes)) : "memory")

#define MBARRIER_WAIT_PARITY(addr, parity) do { \
    uint32_t _m = (uint32_t)(addr); \
    uint32_t _p = (uint32_t)(parity); \
    uint32_t _done; \
    asm volatile( \
        "{\n\t.reg .pred p;\n\t" \
        "mbarrier.try_wait.parity.acquire.cta.shared::cta.b64 p, [%1], %2;\n\t" \
        "selp.b32 %0, 1, 0, p;\n\t}" \
        : "=r"(_done) : "r"(_m), "r"(_p) : "memory"); \
    if (!_done) { \
        asm volatile( \
            "{\n\t.reg .pred P1;\n\t" \
            "WL_%=:\n\t" \
            "mbarrier.try_wait.parity.acquire.cta.shared::cta.b64 P1, [%0], %1, 0x989680;\n\t" \
            "@P1 bra.uni WD_%=;\n\t" \
            "bra.uni WL_%=;\n\t" \
            "WD_%=:\n\t}" \
            :: "r"(_m), "r"(_p) : "memory"); \
    } \
} while(0)

#define FENCE_PROXY_ASYNC() asm volatile("fence.proxy.async.shared::cta;" ::: "memory")

__device__ __forceinline__ void curv_params(const float* __restrict__ craw,
                                            float& kval, float& absk, float& sk, int& branch) {
    float k = -2.0f + 2.0f * (tanhf(craw[0]) + 1.0f);
    kval = k;
    absk = fabsf(k);
    sk = sqrtf(fmaxf(absk, 1e-5f));
    branch = (absk < 0.01f) ? 0 : ((k < 0.0f) ? 1 : 2);
}

// ---------------------------------------------------------------------------
// Tensor-core GEMM: fp16 EC, D = (Ah [+ Al]) * Bh  (USELO toggles the Al term).
// 256 threads (8 warps), CTA tile 128x128, warp tile 32x64, K-chunk 32,
// TMA-1D 3-stage pipeline, 2 CTAs/SM.
// MODE: 0 = QKV (z picks Q/K/V), 1 = scores, 2 = attn @ V (split-K, atomicAdd)
// ---------------------------------------------------------------------------
#define LDT 40
#define BUFSZ (3 * TILE_B)                // Ah Al Bh = 30720
#define NSTAGE 3
#define BAR_OFF (NSTAGE * BUFSZ)          // 92160
#define SMEM_DYN (NSTAGE * BUFSZ + 64)

template<int MODE, int USELO>
__global__ __launch_bounds__(256, 2)
void gemm_tc(const float* __restrict__ bq, const float* __restrict__ bk,
             const float* __restrict__ bv,
             const float* __restrict__ craw, const float* __restrict__ temp,
             float* __restrict__ outp, int zoff) {
    int m0, c0, nch;
    const int n0 = blockIdx.x * 128;
    if (MODE == 2) {
        const int my = blockIdx.y >> 1;          // m-tile 0..15
        const int half = blockIdx.y & 1;         // K-split half
        m0 = my * 128;
        const int kCfull = 4 * (my + 1);         // causal K truncation (even, >= 4)
        nch = kCfull >> 1;                       // >= 2
        c0 = half * nch;
    } else {
        m0 = blockIdx.y * 128;
        c0 = 0;
        nch = 16;
        if (MODE == 1 && blockIdx.x > blockIdx.y) return;   // causal tile skip
    }

    extern __shared__ __align__(128) char smem[];

    const int tid  = threadIdx.x;
    const int wid  = tid >> 5;
    const int lane = tid & 31;
    const int wm   = wid >> 1;       // 0..3 -> rows wm*32..+31
    const int wn   = wid & 1;        // 0..1 -> cols wn*64..+63
    const int z    = blockIdx.z + zoff;

    const unsigned char *tAh, *tAl, *tBh;
    int nktA, nktB, rbA, rbB;
    if (MODE == 0) {
        tAh = g_xh_t; tAl = g_xl_t; nktA = 16; rbA = m0;
        tBh = g_Wh_t[z]; nktB = 16; rbB = n0;
    } else if (MODE == 1) {
        tAh = g_qmh_t; tAl = g_qml_t; nktA = 16; rbA = z * SS + m0;
        tBh = g_kmh_t; nktB = 16; rbB = z * SS + n0;
    } else {
        tAh = g_ah_t; tAl = g_al_t; nktA = 64; rbA = z * SS + m0;
        tBh = g_vTh_t; nktB = 64; rbB = z * DD + n0;
    }

    const uint32_t usm = smem_u32(smem);
    const size_t baseA = (size_t)(rbA >> 7) * nktA;
    const size_t baseB = (size_t)(rbB >> 7) * nktB;

    auto preload = [&](int st, int ch) {
        uint32_t bar = usm + BAR_OFF + st * 8;
        MBARRIER_EXPECT_TX(bar, (USELO ? 3 : 2) * TILE_B);
        uint32_t ub = usm + st * BUFSZ;
        tma1d(ub,              tAh + (baseA + ch) * TILE_B, TILE_B, bar);
        if (USELO)
            tma1d(ub + TILE_B, tAl + (baseA + ch) * TILE_B, TILE_B, bar);
        tma1d(ub + 2 * TILE_B, tBh + (baseB + ch) * TILE_B, TILE_B, bar);
    };

    if (tid == 0) {
        MBARRIER_INIT(usm + BAR_OFF, 1);
        MBARRIER_INIT(usm + BAR_OFF + 8, 1);
        MBARRIER_INIT(usm + BAR_OFF + 16, 1);
    }
    __syncthreads();
    FENCE_PROXY_ASYNC();
    if (tid == 0) {
        preload(0, c0);
        preload(1, c0 + 1);                  // nch >= 2 always
        if (nch > 2) preload(2, c0 + 2);
    }

    float acc[2][8][4] = {};   // warp tile 32x64: 2 m16-tiles x 8 n8-tiles

    const int a_row = lane & 15;
    const int a_ko  = (lane >> 4) << 3;
    const int b_row = (lane & 7) + ((lane >> 4) << 3);
    const int b_ko  = ((lane >> 3) & 1) << 3;

    for (int lc = 0; lc < nch; ++lc) {
        const int st = lc % NSTAGE;
        const int parity = (lc / NSTAGE) & 1;
        MBARRIER_WAIT_PARITY(usm + BAR_OFF + st * 8, parity);

        const uint32_t uAh = usm + st * BUFSZ;
        const uint32_t uAl = uAh + TILE_B;
        const uint32_t uBh = uAh + 2 * TILE_B;

        #pragma unroll
        for (int ks = 0; ks < 2; ++ks) {
            const int kb = ks * 16;
            uint32_t ah[2][4], al[2][4];
            #pragma unroll
            for (int i = 0; i < 2; ++i) {
                uint32_t off = (uint32_t)((wm * 32 + i * 16 + a_row) * LDT + kb + a_ko) * 2;
                ldsm_x4(ah[i], uAh + off);
                if (USELO) ldsm_x4(al[i], uAl + off);
            }
            #pragma unroll
            for (int p = 0; p < 4; ++p) {
                uint32_t off = (uint32_t)((wn * 64 + p * 16 + b_row) * LDT + kb + b_ko) * 2;
                uint32_t rh[4];
                ldsm_x4(rh, uBh + off);
                uint32_t b0h[2] = {rh[0], rh[1]}, b1h[2] = {rh[2], rh[3]};
                #pragma unroll
                for (int i = 0; i < 2; ++i) {
                    mma_f16(acc[i][2*p],   ah[i], b0h);
                    if (USELO) mma_f16(acc[i][2*p], al[i], b0h);
                    mma_f16(acc[i][2*p+1], ah[i], b1h);
                    if (USELO) mma_f16(acc[i][2*p+1], al[i], b1h);
                }
            }
        }
        __syncthreads();                     // all ldsm of stage st consumed
        if (tid == 0 && lc + NSTAGE < nch) preload(st, c0 + lc + NSTAGE);
    }

    // ---- epilogue: 4 passes of 32 rows staged through smem ----
    float (*stg)[132] = (float (*)[132])smem;   // 16896 B, below BAR_OFF

    float kv, absk, sk; int branch;
    float invT = 1.0f;
    if (MODE == 1) {
        curv_params(craw, kv, absk, sk, branch);
        invT = 1.0f / (temp[0] + 1e-8f);
    }
    const float* bias = (MODE == 0) ? ((z == 0) ? bq : (z == 1) ? bk : bv) : nullptr;

    #pragma unroll 1
    for (int h = 0; h < 4; ++h) {
        __syncthreads();
        if (wm == h) {
            #pragma unroll
            for (int i = 0; i < 2; ++i)
                #pragma unroll
                for (int j = 0; j < 8; ++j) {
                    int r = i * 16 + (lane >> 2);
                    int c = wn * 64 + j * 8 + 2 * (lane & 3);
                    stg[r][c]     = acc[i][j][0];
                    stg[r][c+1]   = acc[i][j][1];
                    stg[r+8][c]   = acc[i][j][2];
                    stg[r+8][c+1] = acc[i][j][3];
                }
        }
        __syncthreads();

        if (MODE == 0 && z == 2) {
            // V: write transposed fp16 (hi only) into tiled vT
            #pragma unroll 2
            for (int it = 0; it < 16; ++it) {
                int idx = it * 256 + tid;
                int rr = idx & 31, cc = idx >> 5;       // cc 0..127
                float v = stg[rr][cc] + bias[n0 + cc];
                int m = m0 + h * 32 + rr, b = m >> 11, j = m & (SS - 1);
                put_h(g_vTh_t, b * DD + n0 + cc, j, 64, __float2half(v));
            }
        } else if (MODE == 0) {
            float* dst = (z == 0) ? g_q : g_k;
            #pragma unroll 2
            for (int it = 0; it < 16; ++it) {
                int idx = it * 256 + tid;
                int rr = idx >> 7, cc = idx & 127;
                float v = stg[rr][cc] + bias[n0 + cc];
                dst[(size_t)(m0 + h * 32 + rr) * DD + n0 + cc] = v;
            }
        } else if (MODE == 1) {
            const float* qn2 = g_qn2 + z * SS;
            const float* kn2 = g_kn2 + z * SS;
            float* dst = g_scores + (size_t)z * SS * SS;
            #pragma unroll 2
            for (int it = 0; it < 16; ++it) {
                int idx = it * 256 + tid;
                int rr = idx >> 7, cc = idx & 127;
                float dot = stg[rr][cc];
                float qq = qn2[m0 + h * 32 + rr];
                float kk = kn2[n0 + cc];
                float dist;
                if (branch == 0) {
                    float d2 = fmaxf(qq + kk - 2.0f * dot, 0.0f);
                    dist = sqrtf(d2 + 1e-12f);
                } else if (branch == 1) {
                    float d2 = fmaxf(qq + kk - 2.0f * dot, 0.0f);
                    float den = fmaxf((1.0f - absk * qq) * (1.0f - absk * kk), 1e-5f);
                    float arg = 1.0f + 2.0f * absk * d2 / den;
                    dist = acoshf(fmaxf(arg, 1.0f + 1e-7f)) / sk;
                } else {
                    float c = fminf(fmaxf(absk * dot, -1.0f + 1e-7f), 1.0f - 1e-7f);
                    dist = acosf(c) / sk;
                }
                dst[(size_t)(m0 + h * 32 + rr) * SS + n0 + cc] = -dist * invT;
            }
        } else {
            // split-K partial sum: accumulate into out
            float* dst = outp + (size_t)z * SS * DD;
            #pragma unroll 2
            for (int it = 0; it < 16; ++it) {
                int idx = it * 256 + tid;
                int rr = idx >> 7, cc = idx & 127;
                atomicAdd(&dst[(size_t)(m0 + h * 32 + rr) * DD + n0 + cc], stg[rr][cc]);
            }
        }
    }
}

// ---------------------------------------------------------------------------
// Zero-init of the output region (poisoned by the harness; gemm2 atomic-adds)
// ---------------------------------------------------------------------------
__global__ __launch_bounds__(256)
void zero_out(float4* __restrict__ p) {
    p[blockIdx.x * 256 + threadIdx.x] = make_float4(0.f, 0.f, 0.f, 0.f);
}

// ---------------------------------------------------------------------------
// Fused fp32 -> fp16 split: x (hi+lo), Wq/Wk/Wv (hi only)
// ---------------------------------------------------------------------------
#define NX (BB*SS*DD)
#define NW (DD*DD)

__global__ __launch_bounds__(256)
void split_all(const float* __restrict__ x, const float* __restrict__ wq,
               const float* __restrict__ wk, const float* __restrict__ wv) {
    int i = blockIdx.x * 256 + threadIdx.x;
    if (i < NX) {
        float v = x[i];
        int row = i / DD, col = i % DD;
        __half hi = __float2half(v);
        put_h(g_xh_t, row, col, 16, hi);
        put_h(g_xl_t, row, col, 16, __float2half(v - __half2float(hi)));
    } else {
        const float* src; unsigned char* th; int off;
        if (i < NX + NW)        { src = wq; th = g_Wh_t[0]; off = i - NX; }
        else if (i < NX + 2*NW) { src = wk; th = g_Wh_t[1]; off = i - NX - NW; }
        else                    { src = wv; th = g_Wh_t[2]; off = i - NX - 2*NW; }
        float v = src[off];
        put_h(th, off / DD, off % DD, 16, __float2half(v));
    }
}

// ---------------------------------------------------------------------------
// Projection: q -> tiled fp16 hi+lo; k -> tiled fp16 hi only; plus |.|^2
// ---------------------------------------------------------------------------
__global__ __launch_bounds__(128)
void project_kernel(const float* __restrict__ craw) {
    float kval, absk, sk; int branch;
    curv_params(craw, kval, absk, sk, branch);

    const int row = blockIdx.x;                  // global 0..8191
    const int isq = (blockIdx.y == 0);
    const float* src = (isq ? g_q : g_k) + (size_t)row * DD;
    float* n2out = isq ? g_qn2 : g_kn2;
    const int t = threadIdx.x;

    float v4[4]; float s = 0.f;
    #pragma unroll
    for (int u = 0; u < 4; u++) { v4[u] = src[t + u * 128]; s += v4[u] * v4[u]; }

    __shared__ float red[4];
    #pragma unroll
    for (int o = 16; o > 0; o >>= 1) s += __shfl_xor_sync(0xffffffffu, s, o);
    if ((t & 31) == 0) red[t >> 5] = s;
    __syncthreads();
    float sum = red[0] + red[1] + red[2] + red[3];

    float scale;
    if (branch == 0) {
        scale = 1.0f;
    } else if (branch == 1) {
        float n = sqrtf(sum + 1e-12f);
        float mx = (1.0f - 1e-3f) / sk;
        scale = fminf(1.0f, mx / n);
    } else {
        float n = sqrtf(sum + 1e-12f);
        scale = 1.0f / (n * sk);
    }
    #pragma unroll
    for (int u = 0; u < 4; u++) {
        float pv = v4[u] * scale;
        __half h = __float2half(pv);
        if (isq) {
            put_h(g_qmh_t, row, t + u * 128, 16, h);
            put_h(g_qml_t, row, t + u * 128, 16, __float2half(pv - __half2float(h)));
        } else {
            put_h(g_kmh_t, row, t + u * 128, 16, h);
        }
    }
    if (t == 0) n2out[row] = sum * scale * scale;
}

// ---------------------------------------------------------------------------
// Causal row softmax -> fp32 attention (d_out) + tiled fp16 hi/lo (vectorized)
// ---------------------------------------------------------------------------
__global__ __launch_bounds__(256)
void softmax_kernel(float* __restrict__ attn) {
    const int row = blockIdx.x;         // b*S + i
    const int i = row & (SS - 1);
    const float4* s4 = (const float4*)(g_scores + (size_t)row * SS);
    float4* a4 = (float4*)(attn + (size_t)row * SS);
    const int t = threadIdx.x;

    float vals[8];
    float mx = -1e30f;
    #pragma unroll
    for (int u = 0; u < 2; ++u) {
        int idx = u * 256 + t;
        float4 vv = s4[idx];
        int j0 = idx * 4;
        vals[u*4+0] = (j0     <= i) ? vv.x : -1e30f;
        vals[u*4+1] = (j0 + 1 <= i) ? vv.y : -1e30f;
        vals[u*4+2] = (j0 + 2 <= i) ? vv.z : -1e30f;
        vals[u*4+3] = (j0 + 3 <= i) ? vv.w : -1e30f;
        mx = fmaxf(mx, fmaxf(fmaxf(vals[u*4], vals[u*4+1]), fmaxf(vals[u*4+2], vals[u*4+3])));
    }

    __shared__ float red[8];
    #pragma unroll
    for (int o = 16; o > 0; o >>= 1) mx = fmaxf(mx, __shfl_xor_sync(0xffffffffu, mx, o));
    if ((t & 31) == 0) red[t >> 5] = mx;
    __syncthreads();
    mx = red[0];
    #pragma unroll
    for (int w = 1; w < 8; w++) mx = fmaxf(mx, red[w]);
    __syncthreads();

    float sum = 0.f;
    #pragma unroll
    for (int u = 0; u < 8; ++u) {
        float e = expf(vals[u] - mx);   // masked entries: exp(-1e30) == 0
        vals[u] = e;
        sum += e;
    }
    #pragma unroll
    for (int o = 16; o > 0; o >>= 1) sum += __shfl_xor_sync(0xffffffffu, sum, o);
    if ((t & 31) == 0) red[t >> 5] = sum;
    __syncthreads();
    float tot = 0.f;
    #pragma unroll
    for (int w = 0; w < 8; w++) tot += red[w];
    float inv = 1.0f / tot;

    #pragma unroll
    for (int u = 0; u < 2; ++u) {
        int idx = u * 256 + t;
        int j0 = idx * 4;
        float4 pv;
        pv.x = vals[u*4+0] * inv;
        pv.y = vals[u*4+1] * inv;
        pv.z = vals[u*4+2] * inv;
        pv.w = vals[u*4+3] * inv;
        a4[idx] = pv;
        __half hx = __float2half(pv.x), hy = __float2half(pv.y);
        __half hz = __float2half(pv.z), hw = __float2half(pv.w);
        put_h2(g_ah_t, row, j0,     64, __halves2half2(hx, hy));
        put_h2(g_ah_t, row, j0 + 2, 64, __halves2half2(hz, hw));
        __half lx = __float2half(pv.x - __half2float(hx));
        __half ly = __float2half(pv.y - __half2float(hy));
        __half lz = __float2half(pv.z - __half2float(hz));
        __half lw = __float2half(pv.w - __half2float(hw));
        put_h2(g_al_t, row, j0,     64, __halves2half2(lx, ly));
        put_h2(g_al_t, row, j0 + 2, 64, __halves2half2(lz, lw));
    }
}

// ---------------------------------------------------------------------------
extern "C" void kernel_launch(void* const* d_in, const int* in_sizes, int n_in,
                              void* d_out, int out_size) {
    const float* x    = (const float*)d_in[0];
    const float* Wq   = (const float*)d_in[1];
    const float* bq   = (const float*)d_in[2];
    const float* Wk   = (const float*)d_in[3];
    const float* bk   = (const float*)d_in[4];
    const float* Wv   = (const float*)d_in[5];
    const float* bv   = (const float*)d_in[6];
    const float* craw = (const float*)d_in[7];
    const float* temp = (const float*)d_in[8];

    float* out = (float*)d_out;
    const size_t out_elems = (size_t)BB * SS * DD;
    const size_t attn_elems = (size_t)BB * SS * SS;

    float* attn_ptr;
    if ((size_t)out_size >= out_elems + attn_elems) {
        attn_ptr = out + out_elems;
    } else {
        void* p = nullptr;
        cudaGetSymbolAddress(&p, g_attn_fb);
        attn_ptr = (float*)p;
    }

    cudaFuncSetAttribute(gemm_tc<0,1>, cudaFuncAttributeMaxDynamicSharedMemorySize, SMEM_DYN);
    cudaFuncSetAttribute(gemm_tc<0,0>, cudaFuncAttributeMaxDynamicSharedMemorySize, SMEM_DYN);
    cudaFuncSetAttribute(gemm_tc<1,1>, cudaFuncAttributeMaxDynamicSharedMemorySize, SMEM_DYN);
    cudaFuncSetAttribute(gemm_tc<2,1>, cudaFuncAttributeMaxDynamicSharedMemorySize, SMEM_DYN);

    split_all<<<(NX + 3*NW)/256, 256>>>(x, Wq, Wk, Wv);
    // Q, K projections: 2-product EC
    gemm_tc<0,1><<<dim3(DD/128, (BB*SS)/128, 2), 256, SMEM_DYN>>>(bq, bk, bv, craw, temp, nullptr, 0);
    // V projection: 1-product (output is rounded to fp16 anyway)
    gemm_tc<0,0><<<dim3(DD/128, (BB*SS)/128, 1), 256, SMEM_DYN>>>(bq, bk, bv, craw, temp, nullptr, 2);
    project_kernel<<<dim3(BB*SS, 2), 128>>>(craw);
    gemm_tc<1,1><<<dim3(SS/128, SS/128, BB), 256, SMEM_DYN>>>(bq, bk, bv, craw, temp, nullptr, 0);
    softmax_kernel<<<BB*SS, 256>>>(attn_ptr);
    zero_out<<<(out_elems/4)/256, 256>>>((float4*)out);
    // attn @ V with 2-way split-K, accumulating via atomicAdd
    gemm_tc<2,1><<<dim3(DD/128, 32, BB), 256, SMEM_DYN>>>(bq, bk, bv, craw, temp, out, 0);
}